// round 14
// baseline (speedup 1.0000x reference)
#include <cuda_runtime.h>
#include <cstdint>

#define BB 16
#define LL 24
#define NN 325
#define DDIM 256
#define MROWS (BB*LL*NN)   // 124800 = 975 * 128
#define NPAIRS (BB*NN)     // 5200

typedef unsigned long long ULL;

// ---------------- scratch (device globals) ---------------------------------
__device__ float g_bufQ[MROWS * DDIM];
__device__ float g_bufK[MROWS * DDIM];
__device__ float g_bufV[MROWS * DDIM];
__device__ float g_bufO[MROWS * DDIM];

__device__ unsigned short g_Whi[4][DDIM * DDIM];   // [o][k] bf16, transposed
__device__ unsigned short g_Wlo[4][DDIM * DDIM];

__device__ __align__(16) float g_sum[4][DDIM];
__device__ __align__(16) float g_sumsq[4][DDIM];
__device__ __align__(16) float g_scale[4][DDIM];
__device__ __align__(16) float g_shift[4][DDIM];

// ---------------- helpers ----------------------------------------------------
__device__ __forceinline__ uint32_t smem_u32(const void* p) {
    uint32_t a;
    asm("{ .reg .u64 t; cvta.to.shared.u64 t, %1; cvt.u32.u64 %0, t; }"
        : "=r"(a) : "l"(p));
    return a;
}
__device__ __forceinline__ uint32_t cvt2bf(float lo, float hi) {
    uint32_t r;
    asm("cvt.rn.bf16x2.f32 %0, %1, %2;" : "=r"(r) : "f"(hi), "f"(lo));
    return r;
}
__device__ __forceinline__ void ldsm4(uint32_t* r, uint32_t addr) {
    asm volatile("ldmatrix.sync.aligned.m8n8.x4.shared.b16 {%0,%1,%2,%3}, [%4];"
        : "=r"(r[0]), "=r"(r[1]), "=r"(r[2]), "=r"(r[3]) : "r"(addr));
}
__device__ __forceinline__ void mma_bf16(float* c, const uint32_t* a,
                                         uint32_t b0, uint32_t b1) {
    asm volatile(
        "mma.sync.aligned.m16n8k16.row.col.f32.bf16.bf16.f32 "
        "{%0,%1,%2,%3}, {%4,%5,%6,%7}, {%8,%9}, {%0,%1,%2,%3};"
        : "+f"(c[0]), "+f"(c[1]), "+f"(c[2]), "+f"(c[3])
        : "r"(a[0]), "r"(a[1]), "r"(a[2]), "r"(a[3]), "r"(b0), "r"(b1));
}
__device__ __forceinline__ void cp16(uint32_t dst, const void* src) {
    asm volatile("cp.async.cg.shared.global [%0], [%1], 16;"
                 :: "r"(dst), "l"(src));
}
__device__ __forceinline__ float ex2(float x) {
    float r;
    asm("ex2.approx.f32 %0, %1;" : "=f"(r) : "f"(x));
    return r;
}
#define CP_COMMIT() asm volatile("cp.async.commit_group;" ::: "memory")
#define CP_WAIT1()  asm volatile("cp.async.wait_group 1;" ::: "memory")
#define CP_WAIT0()  asm volatile("cp.async.wait_group 0;" ::: "memory")

// ---------------- zero the BN stat accumulators -----------------------------
__global__ void zero_stats_kernel() {
    int t = threadIdx.x;
#pragma unroll
    for (int s = 0; s < 4; s++) { g_sum[s][t] = 0.f; g_sumsq[s][t] = 0.f; }
}

// ---------------- W convert: fp32 [k][o] -> bf16 hi/lo [o][k], 2 sets -------
__global__ void conv_w_kernel(const float* __restrict__ Wa,
                              const float* __restrict__ Wb, int base) {
    const int set = base + blockIdx.y;
    const float* W = blockIdx.y ? Wb : Wa;
    unsigned short* hi = &g_Whi[set][0];
    unsigned short* lo = &g_Wlo[set][0];
    int idx = blockIdx.x * 256 + threadIdx.x;   // grid (64,2)
#pragma unroll
    for (int i = 0; i < 4; i++) {
        int e = idx + i * 16384;
        int o = e >> 8, k = e & 255;
        float x = W[k * 256 + o];
        unsigned short h;
        asm("cvt.rn.bf16.f32 %0, %1;" : "=h"(h) : "f"(x));
        float fh = __uint_as_float(((uint32_t)h) << 16);
        unsigned short l;
        float res = x - fh;
        asm("cvt.rn.bf16.f32 %0, %1;" : "=h"(l) : "f"(res));
        hi[e] = h;
        lo[e] = l;
    }
}

// ---------------- HMMA bf16x3 GEMM, 2-barrier pipeline ----------------------
// B triple-buffered, ARAW double-buffered (stride 144 = 16B multiple);
// cp.async for chunk kc+2 issued BEFORE the MMA phase of chunk kc.
#define SM_BIAS  0
#define SM_SUM   512
#define SM_SQ    1024
#define SM_AH    2048
#define SM_AL    (SM_AH + 8192)
#define SM_B     (SM_AL + 8192)             // 3 x 16384 = 49152
#define SM_ARAW  (SM_B + 49152)
#define ARAW_STRIDE 144                      // multiple of 16 (cp.async align)
#define ARAW_BUF    (128 * ARAW_STRIDE)     // 18432
#define SM_TOT   (SM_ARAW + 2 * ARAW_BUF)   // 104448 bytes (2 CTA/SM: 204KB)

__device__ __forceinline__ void issue_chunk(
    uint32_t sb, const float* __restrict__ X, int m0,
    const unsigned short* __restrict__ whi,
    const unsigned short* __restrict__ wlo, int n0g, int kc, int tid)
{
    const int bbuf = kc % 3;
    const int abuf = kc & 1;
#pragma unroll
    for (int i = 0; i < 4; i++) {
        int task = tid + (i << 8);
        int half = task >> 9;
        int rem  = task & 511;
        int r = rem >> 2, seg = rem & 3;
        const unsigned short* src = half ? wlo : whi;
        int off = r * 64 + ((seg * 16) ^ (((r >> 1) & 3) << 4));
        cp16(sb + SM_B + bbuf * 16384 + half * 8192 + off,
             &src[(size_t)(n0g + r) * 256 + kc * 32 + seg * 8]);
    }
#pragma unroll
    for (int i = 0; i < 4; i++) {
        int task = tid + (i << 8);
        int r = task >> 3, seg = task & 7;
        cp16(sb + SM_ARAW + abuf * ARAW_BUF + r * ARAW_STRIDE + seg * 16,
             &X[(size_t)(m0 + r) * 256 + kc * 32 + seg * 4]);
    }
    CP_COMMIT();
}

__device__ __forceinline__ void convert_chunk(char* smem, int buf, int tid) {
    const int r = tid >> 1, h = tid & 1;
    const int s = ((r >> 1) & 3) << 4;
    const char* raw = smem + SM_ARAW + buf * ARAW_BUF + r * ARAW_STRIDE + h * 64;
    float4 x0 = *reinterpret_cast<const float4*>(raw);
    float4 x1 = *reinterpret_cast<const float4*>(raw + 16);
    float4 x2 = *reinterpret_cast<const float4*>(raw + 32);
    float4 x3 = *reinterpret_cast<const float4*>(raw + 48);
#pragma unroll
    for (int part = 0; part < 2; part++) {
        float4 a = part ? x2 : x0;
        float4 b = part ? x3 : x1;
        uint32_t h01 = cvt2bf(a.x, a.y);
        uint32_t h23 = cvt2bf(a.z, a.w);
        uint32_t h45 = cvt2bf(b.x, b.y);
        uint32_t h67 = cvt2bf(b.z, b.w);
        float f0 = __uint_as_float(h01 << 16);
        float f1 = __uint_as_float(h01 & 0xFFFF0000u);
        float f2 = __uint_as_float(h23 << 16);
        float f3 = __uint_as_float(h23 & 0xFFFF0000u);
        float f4 = __uint_as_float(h45 << 16);
        float f5 = __uint_as_float(h45 & 0xFFFF0000u);
        float f6 = __uint_as_float(h67 << 16);
        float f7 = __uint_as_float(h67 & 0xFFFF0000u);
        uint32_t l01 = cvt2bf(a.x - f0, a.y - f1);
        uint32_t l23 = cvt2bf(a.z - f2, a.w - f3);
        uint32_t l45 = cvt2bf(b.x - f4, b.y - f5);
        uint32_t l67 = cvt2bf(b.z - f6, b.w - f7);
        int col = (h * 32 + part * 16) ^ s;
        *reinterpret_cast<uint4*>(smem + SM_AH + r * 64 + col) =
            make_uint4(h01, h23, h45, h67);
        *reinterpret_cast<uint4*>(smem + SM_AL + r * 64 + col) =
            make_uint4(l01, l23, l45, l67);
    }
}

__device__ __forceinline__ void gemm_body(
    const float* __restrict__ X,
    const unsigned short* __restrict__ whi,
    const unsigned short* __restrict__ wlo,
    const float* __restrict__ bias, float* __restrict__ Y, int set,
    char* smem, uint32_t sb)
{
    const int tid  = threadIdx.x;
    const int wid  = tid >> 5, lane = tid & 31;
    const int bm   = blockIdx.x >> 1;
    const int bn   = blockIdx.x & 1;
    const int m0   = bm * 128;
    const int n0g  = bn * 128;
    const int warp_m = wid & 3;
    const int warp_n = wid >> 2;

    float* bias_s = (float*)(smem + SM_BIAS);
    float* sum_s  = (float*)(smem + SM_SUM);
    float* sq_s   = (float*)(smem + SM_SQ);
    if (tid < 128) {
        bias_s[tid] = bias[n0g + tid];
        sum_s[tid] = 0.f;
        sq_s[tid]  = 0.f;
    }

    float acc[2][8][4];
#pragma unroll
    for (int a = 0; a < 2; a++)
#pragma unroll
        for (int b = 0; b < 8; b++)
#pragma unroll
            for (int c = 0; c < 4; c++) acc[a][b][c] = 0.f;

    issue_chunk(sb, X, m0, whi, wlo, n0g, 0, tid);
    issue_chunk(sb, X, m0, whi, wlo, n0g, 1, tid);
    CP_WAIT1();
    __syncthreads();
    convert_chunk(smem, 0, tid);
    __syncthreads();

    const int a_row = (warp_m * 32) + (lane & 7) + ((lane >> 3) & 1) * 8;
    const int a_kof = (lane >> 4) * 16;
    const int b_row = (warp_n * 64) + (lane & 7) + ((lane >> 4) & 1) * 8;
    const int b_kof = ((lane >> 3) & 1) * 16;
    const int sA = ((a_row >> 1) & 3) << 4;
    const int sB = ((b_row >> 1) & 3) << 4;
    const uint32_t aHb = sb + SM_AH + a_row * 64;
    const uint32_t aLb = sb + SM_AL + a_row * 64;

    for (int kc = 0; kc < 8; kc++) {
        // issue chunk kc+2 early: B[(kc+2)%3] and ARAW[kc&1] are free
        if (kc < 6) issue_chunk(sb, X, m0, whi, wlo, n0g, kc + 2, tid);

        const uint32_t bHb = sb + SM_B + (kc % 3) * 16384 + b_row * 64;
        const uint32_t bLb = bHb + 8192;

#pragma unroll
        for (int ks = 0; ks < 2; ks++) {
            const int kb = ks * 32;
            uint32_t ah[2][4], al[2][4];
            const uint32_t koA = (uint32_t)((kb + a_kof) ^ sA);
#pragma unroll
            for (int mi = 0; mi < 2; mi++) {
                ldsm4(ah[mi], aHb + mi * 1024 + koA);
                ldsm4(al[mi], aLb + mi * 1024 + koA);
            }
            const uint32_t koB = (uint32_t)((kb + b_kof) ^ sB);
#pragma unroll
            for (int g = 0; g < 4; g++) {
                uint32_t bh[4], bl[4];
                ldsm4(bh, bHb + g * 1024 + koB);
                ldsm4(bl, bLb + g * 1024 + koB);
                mma_bf16(acc[0][2 * g],     ah[0], bh[0], bh[1]);
                mma_bf16(acc[1][2 * g],     ah[1], bh[0], bh[1]);
                mma_bf16(acc[0][2 * g + 1], ah[0], bh[2], bh[3]);
                mma_bf16(acc[1][2 * g + 1], ah[1], bh[2], bh[3]);
                mma_bf16(acc[0][2 * g],     al[0], bh[0], bh[1]);
                mma_bf16(acc[1][2 * g],     al[1], bh[0], bh[1]);
                mma_bf16(acc[0][2 * g + 1], al[0], bh[2], bh[3]);
                mma_bf16(acc[1][2 * g + 1], al[1], bh[2], bh[3]);
                mma_bf16(acc[0][2 * g],     ah[0], bl[0], bl[1]);
                mma_bf16(acc[1][2 * g],     ah[1], bl[0], bl[1]);
                mma_bf16(acc[0][2 * g + 1], ah[0], bl[2], bl[3]);
                mma_bf16(acc[1][2 * g + 1], ah[1], bl[2], bl[3]);
            }
        }
        __syncthreads();   // all MMA reads of AH/AL + B[kc%3] done

        if (kc < 7) {
            if (kc < 6) CP_WAIT1(); else CP_WAIT0();   // chunk kc+1 landed
            convert_chunk(smem, (kc + 1) & 1, tid);
            __syncthreads();                            // AH/AL ready
        }
    }

    // ---- epilogue: bias, store, BN stats ----
    const int qrow = lane >> 2;
    const int qcol = (lane & 3) * 2;
#pragma unroll
    for (int g = 0; g < 4; g++) {
#pragma unroll
        for (int sub = 0; sub < 2; sub++) {
            const int ncol = warp_n * 64 + g * 16 + sub * 8 + qcol;
            const float b0 = bias_s[ncol], b1 = bias_s[ncol + 1];
            float p0 = 0.f, p1 = 0.f, q0 = 0.f, q1 = 0.f;
#pragma unroll
            for (int mi = 0; mi < 2; mi++) {
                const float* a = acc[mi][2 * g + sub];
                float y00 = a[0] + b0, y01 = a[1] + b1;
                float y10 = a[2] + b0, y11 = a[3] + b1;
                const int r = m0 + warp_m * 32 + mi * 16 + qrow;
                *reinterpret_cast<float2*>(&Y[(size_t)r * 256 + n0g + ncol]) =
                    make_float2(y00, y01);
                *reinterpret_cast<float2*>(&Y[(size_t)(r + 8) * 256 + n0g + ncol]) =
                    make_float2(y10, y11);
                p0 += y00 + y10;
                p1 += y01 + y11;
                q0 += y00 * y00 + y10 * y10;
                q1 += y01 * y01 + y11 * y11;
            }
#pragma unroll
            for (int d = 4; d < 32; d <<= 1) {
                p0 += __shfl_xor_sync(0xffffffffu, p0, d);
                p1 += __shfl_xor_sync(0xffffffffu, p1, d);
                q0 += __shfl_xor_sync(0xffffffffu, q0, d);
                q1 += __shfl_xor_sync(0xffffffffu, q1, d);
            }
            if (lane < 4) {
                atomicAdd(&sum_s[ncol], p0);
                atomicAdd(&sum_s[ncol + 1], p1);
                atomicAdd(&sq_s[ncol], q0);
                atomicAdd(&sq_s[ncol + 1], q1);
            }
        }
    }
    __syncthreads();
    if (tid < 128) {
        atomicAdd(&g_sum[set][n0g + tid], sum_s[tid]);
        atomicAdd(&g_sumsq[set][n0g + tid], sq_s[tid]);
    }
}

__global__ __launch_bounds__(256, 2) void gemm_qkv_kernel(
    const float* __restrict__ Xq, const float* __restrict__ Xk,
    const float* __restrict__ Xv,
    const float* __restrict__ bq, const float* __restrict__ bk,
    const float* __restrict__ bv)
{
    extern __shared__ char smem[];
    const uint32_t sb = smem_u32(smem);
    const int set = blockIdx.y;
    const float* X = (set == 0) ? Xq : (set == 1) ? Xk : Xv;
    const float* bias = (set == 0) ? bq : (set == 1) ? bk : bv;
    float* Y = (set == 0) ? g_bufQ : (set == 1) ? g_bufK : g_bufV;
    gemm_body(X, &g_Whi[set][0], &g_Wlo[set][0], bias, Y, set, smem, sb);
}

// output projection writes directly to d_out (Z); normalized in place later
__global__ __launch_bounds__(256, 2) void gemm_o_kernel(
    const float* __restrict__ bo, float* __restrict__ out)
{
    extern __shared__ char smem[];
    const uint32_t sb = smem_u32(smem);
    gemm_body(g_bufO, &g_Whi[3][0], &g_Wlo[3][0], bo, out, 3, smem, sb);
}

// ---------------- finalize BN ------------------------------------------------
__global__ void finalize_bn3_kernel(
    const float* __restrict__ g0, const float* __restrict__ be0,
    const float* __restrict__ g1, const float* __restrict__ be1,
    const float* __restrict__ g2, const float* __restrict__ be2)
{
    int set = blockIdx.x;
    const float* gamma = (set == 0) ? g0 : (set == 1) ? g1 : g2;
    const float* beta  = (set == 0) ? be0 : (set == 1) ? be1 : be2;
    int o = threadIdx.x;
    const float invM = 1.f / (float)MROWS;
    float mu  = g_sum[set][o] * invM;
    float var = g_sumsq[set][o] * invM - mu * mu;
    float sc = gamma[o] * rsqrtf(var + 1e-5f);
    g_scale[set][o] = sc;
    g_shift[set][o] = beta[o] - mu * sc;
}

__global__ void finalize_bn_kernel(const float* __restrict__ gamma,
                                   const float* __restrict__ beta, int set) {
    int o = threadIdx.x;
    const float invM = 1.f / (float)MROWS;
    float mu  = g_sum[set][o] * invM;
    float var = g_sumsq[set][o] * invM - mu * mu;
    float sc = gamma[o] * rsqrtf(var + 1e-5f);
    g_scale[set][o] = sc;
    g_shift[set][o] = beta[o] - mu * sc;
}

// ---------------- attention (R12, unchanged) ---------------------------------
__device__ __forceinline__ float4 norm_relu4(float4 y, float4 s, float4 t) {
    float4 r;
    r.x = fmaxf(fmaf(y.x, s.x, t.x), 0.f);
    r.y = fmaxf(fmaf(y.y, s.y, t.y), 0.f);
    r.z = fmaxf(fmaf(y.z, s.z, t.z), 0.f);
    r.w = fmaxf(fmaf(y.w, s.w, t.w), 0.f);
    return r;
}

#define ATT_ROW 196
#define ATT_TEN (32 * ATT_ROW)
#define OUT_ROW 260
#define ATT_OUT (24 * OUT_ROW)
#define ATT_SMEM ((3 * ATT_TEN + ATT_OUT) * 4)   // 100224 bytes

__global__ __launch_bounds__(384, 2) void attn_kernel(
    const float* __restrict__ Yq, const float* __restrict__ Yk,
    const float* __restrict__ Yv, float* __restrict__ O)
{
    extern __shared__ float asm_s[];
    float* qs = asm_s;
    float* ks = asm_s + ATT_TEN;
    float* vs = asm_s + 2 * ATT_TEN;
    float* out_s = asm_s + 3 * ATT_TEN;

    const int tid = threadIdx.x;
    const int pair = blockIdx.x;
    const int b = pair / NN;
    const int n = pair - b * NN;
    const float QSC = 0.17677669529663687f * 1.4426950408889634f;

#pragma unroll
    for (int i = 0; i < 4; i++) {
        int f  = tid + i * 384;
        int l  = f >> 6;
        int q4 = f & 63;
        int d0 = q4 << 2;
        int c  = d0 >> 3, h0 = d0 & 7;
        int so = c * ATT_ROW + l * 8 + h0;
        size_t g = ((size_t)(b * LL + l) * NN + n) * DDIM + d0;

        float4 sq = *reinterpret_cast<const float4*>(&g_scale[0][d0]);
        float4 tq = *reinterpret_cast<const float4*>(&g_shift[0][d0]);
        float4 sk = *reinterpret_cast<const float4*>(&g_scale[1][d0]);
        float4 tk = *reinterpret_cast<const float4*>(&g_shift[1][d0]);
        float4 sv = *reinterpret_cast<const float4*>(&g_scale[2][d0]);
        float4 tv = *reinterpret_cast<const float4*>(&g_shift[2][d0]);

        float4 yq = *reinterpret_cast<const float4*>(&Yq[g]);
        float4 yk = *reinterpret_cast<const float4*>(&Yk[g]);
        float4 yv = *reinterpret_cast<const float4*>(&Yv[g]);

        float4 qn = norm_relu4(yq, sq, tq);
        qn.x *= QSC; qn.y *= QSC; qn.z *= QSC; qn.w *= QSC;
        *reinterpret_cast<float4*>(&qs[so]) = qn;
        *reinterpret_cast<float4*>(&ks[so]) = norm_relu4(yk, sk, tk);
        *reinterpret_cast<float4*>(&vs[so]) = norm_relu4(yv, sv, tv);
    }
    __syncthreads();

    const int c0 = tid / 24;
    const int lf = tid - c0 * 24;

#pragma unroll
    for (int t = 0; t < 2; t++) {
        const int c = c0 + t * 16;
        const float* qr = &qs[c * ATT_ROW + lf * 8];
        float4 q0 = *reinterpret_cast<const float4*>(qr);
        float4 q1 = *reinterpret_cast<const float4*>(qr + 4);

        float sc[24];
        float mx = -1e30f;
#pragma unroll
        for (int pp = 0; pp < 24; pp++) {
            const float* kr = &ks[c * ATT_ROW + pp * 8];
            float4 k0 = *reinterpret_cast<const float4*>(kr);
            float4 k1 = *reinterpret_cast<const float4*>(kr + 4);
            float s = q0.x * k0.x + q0.y * k0.y + q0.z * k0.z + q0.w * k0.w +
                      q1.x * k1.x + q1.y * k1.y + q1.z * k1.z + q1.w * k1.w;
            sc[pp] = s;
            mx = fmaxf(mx, s);
        }
        float ssum = 0.f;
#pragma unroll
        for (int pp = 0; pp < 24; pp++) {
            float e = ex2(sc[pp] - mx);
            sc[pp] = e;
            ssum += e;
        }
        float inv = 1.f / ssum;
        float o[8] = {0.f, 0.f, 0.f, 0.f, 0.f, 0.f, 0.f, 0.f};
#pragma unroll
        for (int pp = 0; pp < 24; pp++) {
            float a = sc[pp] * inv;
            const float* vr = &vs[c * ATT_ROW + pp * 8];
            float4 v0 = *reinterpret_cast<const float4*>(vr);
            float4 v1 = *reinterpret_cast<const float4*>(vr + 4);
            o[0] = fmaf(a, v0.x, o[0]);
            o[1] = fmaf(a, v0.y, o[1]);
            o[2] = fmaf(a, v0.z, o[2]);
            o[3] = fmaf(a, v0.w, o[3]);
            o[4] = fmaf(a, v1.x, o[4]);
            o[5] = fmaf(a, v1.y, o[5]);
            o[6] = fmaf(a, v1.z, o[6]);
            o[7] = fmaf(a, v1.w, o[7]);
        }
        float* op = &out_s[lf * OUT_ROW + c * 8];
        *reinterpret_cast<float4*>(op)     = make_float4(o[0], o[1], o[2], o[3]);
        *reinterpret_cast<float4*>(op + 4) = make_float4(o[4], o[5], o[6], o[7]);
    }
    __syncthreads();

#pragma unroll
    for (int i = 0; i < 4; i++) {
        int f  = tid + i * 384;
        int l  = f >> 6;
        int q4 = f & 63;
        float4 v = *reinterpret_cast<const float4*>(&out_s[l * OUT_ROW + q4 * 4]);
        size_t g = ((size_t)(b * LL + l) * NN + n) * DDIM + q4 * 4;
        *reinterpret_cast<float4*>(&O[g]) = v;
    }
}

// ---------------- final normalize + relu, IN PLACE on d_out -----------------
__global__ __launch_bounds__(256) void norm_out_kernel(float* __restrict__ out)
{
    size_t i = (size_t)blockIdx.x * 256 + threadIdx.x;
    size_t idx = i * 4;
    int d = (int)(idx & 255);
    float4 z = *reinterpret_cast<const float4*>(&out[idx]);
    float4 s = *reinterpret_cast<const float4*>(&g_scale[3][d]);
    float4 t = *reinterpret_cast<const float4*>(&g_shift[3][d]);
    float4 r;
    r.x = fmaxf(fmaf(z.x, s.x, t.x), 0.f);
    r.y = fmaxf(fmaf(z.y, s.y, t.y), 0.f);
    r.z = fmaxf(fmaf(z.z, s.z, t.z), 0.f);
    r.w = fmaxf(fmaf(z.w, s.w, t.w), 0.f);
    *reinterpret_cast<float4*>(&out[idx]) = r;
}

// ---------------- launch ------------------------------------------------------
extern "C" void kernel_launch(void* const* d_in, const int* in_sizes, int n_in,
                              void* d_out, int out_size)
{
    const float* x   = (const float*)d_in[0];
    const float* sp  = (const float*)d_in[1];
    const float* sf  = (const float*)d_in[2];
    const float* Wq  = (const float*)d_in[3];
    const float* bq  = (const float*)d_in[4];
    const float* gq  = (const float*)d_in[5];
    const float* beq = (const float*)d_in[6];
    const float* Wk  = (const float*)d_in[7];
    const float* bk  = (const float*)d_in[8];
    const float* gk  = (const float*)d_in[9];
    const float* bek = (const float*)d_in[10];
    const float* Wv  = (const float*)d_in[11];
    const float* bv  = (const float*)d_in[12];
    const float* gv  = (const float*)d_in[13];
    const float* bev = (const float*)d_in[14];
    const float* Wo  = (const float*)d_in[15];
    const float* bo  = (const float*)d_in[16];
    const float* go  = (const float*)d_in[17];
    const float* beo = (const float*)d_in[18];
    float* out = (float*)d_out;

    float *Yq, *Yk, *Yv, *O;
    cudaGetSymbolAddress((void**)&Yq, g_bufQ);
    cudaGetSymbolAddress((void**)&Yk, g_bufK);
    cudaGetSymbolAddress((void**)&Yv, g_bufV);
    cudaGetSymbolAddress((void**)&O,  g_bufO);

    cudaFuncSetAttribute(gemm_qkv_kernel,
                         cudaFuncAttributeMaxDynamicSharedMemorySize, SM_TOT);
    cudaFuncSetAttribute(gemm_o_kernel,
                         cudaFuncAttributeMaxDynamicSharedMemorySize, SM_TOT);
    cudaFuncSetAttribute(attn_kernel,
                         cudaFuncAttributeMaxDynamicSharedMemorySize, ATT_SMEM);

    conv_w_kernel<<<dim3(64, 2), 256>>>(Wq, Wk, 0);
    conv_w_kernel<<<dim3(64, 2), 256>>>(Wv, Wo, 2);
    zero_stats_kernel<<<1, 256>>>();

    const int gblocks = (MROWS / 128) * 2;   // 1950

    gemm_qkv_kernel<<<dim3(gblocks, 3), 256, SM_TOT>>>(sf, sp, x, bq, bk, bv);

    finalize_bn3_kernel<<<3, 256>>>(gq, beq, gk, bek, gv, bev);

    attn_kernel<<<NPAIRS, 384, ATT_SMEM>>>(Yq, Yk, Yv, O);

    gemm_o_kernel<<<gblocks, 256, SM_TOT>>>(bo, out);
    finalize_bn_kernel<<<1, 256>>>(go, beo, 3);

    norm_out_kernel<<<(MROWS * DDIM) / (4 * 256), 256>>>(out);
}

// round 15
// speedup vs baseline: 1.0317x; 1.0317x over previous
#include <cuda_runtime.h>
#include <cstdint>

#define BB 16
#define LL 24
#define NN 325
#define DDIM 256
#define MROWS (BB*LL*NN)   // 124800 = 975 * 128
#define NPAIRS (BB*NN)     // 5200

typedef unsigned long long ULL;

// ---------------- scratch (device globals) ---------------------------------
__device__ float g_bufQ[MROWS * DDIM];
__device__ float g_bufK[MROWS * DDIM];
__device__ float g_bufV[MROWS * DDIM];
__device__ float g_bufO[MROWS * DDIM];   // aliased: [0..] Ohi ushorts, [MROWS*DDIM..] Olo

__device__ unsigned short g_Whi[4][DDIM * DDIM];   // [o][k] bf16, transposed
__device__ unsigned short g_Wlo[4][DDIM * DDIM];

__device__ __align__(16) float g_sum[4][DDIM];
__device__ __align__(16) float g_sumsq[4][DDIM];
__device__ __align__(16) float g_scale[4][DDIM];
__device__ __align__(16) float g_shift[4][DDIM];

// ---------------- helpers ----------------------------------------------------
__device__ __forceinline__ uint32_t smem_u32(const void* p) {
    uint32_t a;
    asm("{ .reg .u64 t; cvta.to.shared.u64 t, %1; cvt.u32.u64 %0, t; }"
        : "=r"(a) : "l"(p));
    return a;
}
__device__ __forceinline__ uint32_t cvt2bf(float lo, float hi) {
    uint32_t r;
    asm("cvt.rn.bf16x2.f32 %0, %1, %2;" : "=r"(r) : "f"(hi), "f"(lo));
    return r;
}
__device__ __forceinline__ void ldsm4(uint32_t* r, uint32_t addr) {
    asm volatile("ldmatrix.sync.aligned.m8n8.x4.shared.b16 {%0,%1,%2,%3}, [%4];"
        : "=r"(r[0]), "=r"(r[1]), "=r"(r[2]), "=r"(r[3]) : "r"(addr));
}
__device__ __forceinline__ void mma_bf16(float* c, const uint32_t* a,
                                         uint32_t b0, uint32_t b1) {
    asm volatile(
        "mma.sync.aligned.m16n8k16.row.col.f32.bf16.bf16.f32 "
        "{%0,%1,%2,%3}, {%4,%5,%6,%7}, {%8,%9}, {%0,%1,%2,%3};"
        : "+f"(c[0]), "+f"(c[1]), "+f"(c[2]), "+f"(c[3])
        : "r"(a[0]), "r"(a[1]), "r"(a[2]), "r"(a[3]), "r"(b0), "r"(b1));
}
__device__ __forceinline__ void cp16(uint32_t dst, const void* src) {
    asm volatile("cp.async.cg.shared.global [%0], [%1], 16;"
                 :: "r"(dst), "l"(src));
}
__device__ __forceinline__ float ex2(float x) {
    float r;
    asm("ex2.approx.f32 %0, %1;" : "=f"(r) : "f"(x));
    return r;
}
#define CP_COMMIT() asm volatile("cp.async.commit_group;" ::: "memory")
#define CP_WAIT1()  asm volatile("cp.async.wait_group 1;" ::: "memory")
#define CP_WAIT0()  asm volatile("cp.async.wait_group 0;" ::: "memory")

// ---------------- zero the BN stat accumulators -----------------------------
__global__ void zero_stats_kernel() {
    int t = threadIdx.x;
#pragma unroll
    for (int s = 0; s < 4; s++) { g_sum[s][t] = 0.f; g_sumsq[s][t] = 0.f; }
}

// ---------------- W convert: fp32 [k][o] -> bf16 hi/lo [o][k], 2 sets -------
__global__ void conv_w_kernel(const float* __restrict__ Wa,
                              const float* __restrict__ Wb, int base) {
    const int set = base + blockIdx.y;
    const float* W = blockIdx.y ? Wb : Wa;
    unsigned short* hi = &g_Whi[set][0];
    unsigned short* lo = &g_Wlo[set][0];
    int idx = blockIdx.x * 256 + threadIdx.x;   // grid (64,2)
#pragma unroll
    for (int i = 0; i < 4; i++) {
        int e = idx + i * 16384;
        int o = e >> 8, k = e & 255;
        float x = W[k * 256 + o];
        unsigned short h;
        asm("cvt.rn.bf16.f32 %0, %1;" : "=h"(h) : "f"(x));
        float fh = __uint_as_float(((uint32_t)h) << 16);
        unsigned short l;
        float res = x - fh;
        asm("cvt.rn.bf16.f32 %0, %1;" : "=h"(l) : "f"(res));
        hi[e] = h;
        lo[e] = l;
    }
}

// ---------------- HMMA bf16x3 GEMM (R10 mainloop, proven 434us) -------------
#define SM_BIAS  0
#define SM_SUM   512
#define SM_SQ    1024
#define SM_AH    2048
#define SM_AL    (SM_AH + 8192)
#define SM_B     (SM_AL + 8192)             // 2 x 16384 = 32768
#define SM_ARAW  (SM_B + 32768)
#define ARAW_STRIDE 144
#define ARAW_BUF    (128 * ARAW_STRIDE)     // 18432
#define SM_TOT   (SM_ARAW + 2 * ARAW_BUF)   // 88064 bytes

__device__ __forceinline__ void issue_chunk(
    uint32_t sb, const float* __restrict__ X, int m0,
    const unsigned short* __restrict__ whi,
    const unsigned short* __restrict__ wlo, int n0g, int kc, int tid)
{
    const int buf = kc & 1;
#pragma unroll
    for (int i = 0; i < 4; i++) {
        int task = tid + (i << 8);
        int half = task >> 9;
        int rem  = task & 511;
        int r = rem >> 2, seg = rem & 3;
        const unsigned short* src = half ? wlo : whi;
        int off = r * 64 + ((seg * 16) ^ (((r >> 1) & 3) << 4));
        cp16(sb + SM_B + buf * 16384 + half * 8192 + off,
             &src[(size_t)(n0g + r) * 256 + kc * 32 + seg * 8]);
    }
#pragma unroll
    for (int i = 0; i < 4; i++) {
        int task = tid + (i << 8);
        int r = task >> 3, seg = task & 7;
        cp16(sb + SM_ARAW + buf * ARAW_BUF + r * ARAW_STRIDE + seg * 16,
             &X[(size_t)(m0 + r) * 256 + kc * 32 + seg * 4]);
    }
    CP_COMMIT();
}

__device__ __forceinline__ void convert_chunk(char* smem, int buf, int tid) {
    const int r = tid >> 1, h = tid & 1;
    const int s = ((r >> 1) & 3) << 4;
    const char* raw = smem + SM_ARAW + buf * ARAW_BUF + r * ARAW_STRIDE + h * 64;
    float4 x0 = *reinterpret_cast<const float4*>(raw);
    float4 x1 = *reinterpret_cast<const float4*>(raw + 16);
    float4 x2 = *reinterpret_cast<const float4*>(raw + 32);
    float4 x3 = *reinterpret_cast<const float4*>(raw + 48);
#pragma unroll
    for (int part = 0; part < 2; part++) {
        float4 a = part ? x2 : x0;
        float4 b = part ? x3 : x1;
        uint32_t h01 = cvt2bf(a.x, a.y);
        uint32_t h23 = cvt2bf(a.z, a.w);
        uint32_t h45 = cvt2bf(b.x, b.y);
        uint32_t h67 = cvt2bf(b.z, b.w);
        float f0 = __uint_as_float(h01 << 16);
        float f1 = __uint_as_float(h01 & 0xFFFF0000u);
        float f2 = __uint_as_float(h23 << 16);
        float f3 = __uint_as_float(h23 & 0xFFFF0000u);
        float f4 = __uint_as_float(h45 << 16);
        float f5 = __uint_as_float(h45 & 0xFFFF0000u);
        float f6 = __uint_as_float(h67 << 16);
        float f7 = __uint_as_float(h67 & 0xFFFF0000u);
        uint32_t l01 = cvt2bf(a.x - f0, a.y - f1);
        uint32_t l23 = cvt2bf(a.z - f2, a.w - f3);
        uint32_t l45 = cvt2bf(b.x - f4, b.y - f5);
        uint32_t l67 = cvt2bf(b.z - f6, b.w - f7);
        int col = (h * 32 + part * 16) ^ s;
        *reinterpret_cast<uint4*>(smem + SM_AH + r * 64 + col) =
            make_uint4(h01, h23, h45, h67);
        *reinterpret_cast<uint4*>(smem + SM_AL + r * 64 + col) =
            make_uint4(l01, l23, l45, l67);
    }
}

// shared MMA + epilogue stage (A/B tiles already in smem per chunk)
__device__ __forceinline__ void mma_chunk(
    float acc[2][8][4], uint32_t aHb, uint32_t aLb, uint32_t bHb, uint32_t bLb,
    int a_kof, int b_kof, int sA, int sB)
{
#pragma unroll
    for (int ks = 0; ks < 2; ks++) {
        const int kb = ks * 32;
        uint32_t ah[2][4], al[2][4];
        const uint32_t koA = (uint32_t)((kb + a_kof) ^ sA);
#pragma unroll
        for (int mi = 0; mi < 2; mi++) {
            ldsm4(ah[mi], aHb + mi * 1024 + koA);
            ldsm4(al[mi], aLb + mi * 1024 + koA);
        }
        const uint32_t koB = (uint32_t)((kb + b_kof) ^ sB);
#pragma unroll
        for (int g = 0; g < 4; g++) {
            uint32_t bh[4], bl[4];
            ldsm4(bh, bHb + g * 1024 + koB);
            ldsm4(bl, bLb + g * 1024 + koB);
            mma_bf16(acc[0][2 * g],     ah[0], bh[0], bh[1]);
            mma_bf16(acc[1][2 * g],     ah[1], bh[0], bh[1]);
            mma_bf16(acc[0][2 * g + 1], ah[0], bh[2], bh[3]);
            mma_bf16(acc[1][2 * g + 1], ah[1], bh[2], bh[3]);
            mma_bf16(acc[0][2 * g],     al[0], bh[0], bh[1]);
            mma_bf16(acc[1][2 * g],     al[1], bh[0], bh[1]);
            mma_bf16(acc[0][2 * g + 1], al[0], bh[2], bh[3]);
            mma_bf16(acc[1][2 * g + 1], al[1], bh[2], bh[3]);
            mma_bf16(acc[0][2 * g],     ah[0], bl[0], bl[1]);
            mma_bf16(acc[1][2 * g],     ah[1], bl[0], bl[1]);
            mma_bf16(acc[0][2 * g + 1], ah[0], bl[2], bl[3]);
            mma_bf16(acc[1][2 * g + 1], ah[1], bl[2], bl[3]);
        }
    }
}

__device__ __forceinline__ void gemm_epilogue(
    float acc[2][8][4], float* bias_s, float* sum_s, float* sq_s,
    float* __restrict__ Y, int m0, int n0g, int set,
    int warp_m, int warp_n, int lane, int tid)
{
    const int qrow = lane >> 2;
    const int qcol = (lane & 3) * 2;
#pragma unroll
    for (int g = 0; g < 4; g++) {
#pragma unroll
        for (int sub = 0; sub < 2; sub++) {
            const int ncol = warp_n * 64 + g * 16 + sub * 8 + qcol;
            const float b0 = bias_s[ncol], b1 = bias_s[ncol + 1];
            float p0 = 0.f, p1 = 0.f, q0 = 0.f, q1 = 0.f;
#pragma unroll
            for (int mi = 0; mi < 2; mi++) {
                const float* a = acc[mi][2 * g + sub];
                float y00 = a[0] + b0, y01 = a[1] + b1;
                float y10 = a[2] + b0, y11 = a[3] + b1;
                const int r = m0 + warp_m * 32 + mi * 16 + qrow;
                *reinterpret_cast<float2*>(&Y[(size_t)r * 256 + n0g + ncol]) =
                    make_float2(y00, y01);
                *reinterpret_cast<float2*>(&Y[(size_t)(r + 8) * 256 + n0g + ncol]) =
                    make_float2(y10, y11);
                p0 += y00 + y10;
                p1 += y01 + y11;
                q0 += y00 * y00 + y10 * y10;
                q1 += y01 * y01 + y11 * y11;
            }
#pragma unroll
            for (int d = 4; d < 32; d <<= 1) {
                p0 += __shfl_xor_sync(0xffffffffu, p0, d);
                p1 += __shfl_xor_sync(0xffffffffu, p1, d);
                q0 += __shfl_xor_sync(0xffffffffu, q0, d);
                q1 += __shfl_xor_sync(0xffffffffu, q1, d);
            }
            if (lane < 4) {
                atomicAdd(&sum_s[ncol], p0);
                atomicAdd(&sum_s[ncol + 1], p1);
                atomicAdd(&sq_s[ncol], q0);
                atomicAdd(&sq_s[ncol + 1], q1);
            }
        }
    }
    __syncthreads();
    if (tid < 128) {
        atomicAdd(&g_sum[set][n0g + tid], sum_s[tid]);
        atomicAdd(&g_sumsq[set][n0g + tid], sq_s[tid]);
    }
}

// QKV GEMM: fp32 input, in-kernel hi/lo conversion (R10-proven pipeline)
__global__ __launch_bounds__(256, 2) void gemm_qkv_kernel(
    const float* __restrict__ Xq, const float* __restrict__ Xk,
    const float* __restrict__ Xv,
    const float* __restrict__ bq, const float* __restrict__ bk,
    const float* __restrict__ bv)
{
    extern __shared__ char smem[];
    const uint32_t sb = smem_u32(smem);
    const int set = blockIdx.y;
    const float* X = (set == 0) ? Xq : (set == 1) ? Xk : Xv;
    const float* bias = (set == 0) ? bq : (set == 1) ? bk : bv;
    float* Y = (set == 0) ? g_bufQ : (set == 1) ? g_bufK : g_bufV;
    const unsigned short* whi = &g_Whi[set][0];
    const unsigned short* wlo = &g_Wlo[set][0];

    const int tid  = threadIdx.x;
    const int wid  = tid >> 5, lane = tid & 31;
    const int m0   = (blockIdx.x >> 1) * 128;
    const int n0g  = (blockIdx.x & 1) * 128;
    const int warp_m = wid & 3;
    const int warp_n = wid >> 2;

    float* bias_s = (float*)(smem + SM_BIAS);
    float* sum_s  = (float*)(smem + SM_SUM);
    float* sq_s   = (float*)(smem + SM_SQ);
    if (tid < 128) {
        bias_s[tid] = bias[n0g + tid];
        sum_s[tid] = 0.f;
        sq_s[tid]  = 0.f;
    }

    float acc[2][8][4];
#pragma unroll
    for (int a = 0; a < 2; a++)
#pragma unroll
        for (int b = 0; b < 8; b++)
#pragma unroll
            for (int c = 0; c < 4; c++) acc[a][b][c] = 0.f;

    issue_chunk(sb, X, m0, whi, wlo, n0g, 0, tid);
    issue_chunk(sb, X, m0, whi, wlo, n0g, 1, tid);
    CP_WAIT1();
    __syncthreads();
    convert_chunk(smem, 0, tid);
    __syncthreads();

    const int a_row = (warp_m * 32) + (lane & 7) + ((lane >> 3) & 1) * 8;
    const int a_kof = (lane >> 4) * 16;
    const int b_row = (warp_n * 64) + (lane & 7) + ((lane >> 4) & 1) * 8;
    const int b_kof = ((lane >> 3) & 1) * 16;
    const int sA = ((a_row >> 1) & 3) << 4;
    const int sB = ((b_row >> 1) & 3) << 4;
    const uint32_t aHb = sb + SM_AH + a_row * 64;
    const uint32_t aLb = sb + SM_AL + a_row * 64;

    for (int kc = 0; kc < 8; kc++) {
        const uint32_t bHb = sb + SM_B + (kc & 1) * 16384 + b_row * 64;
        mma_chunk(acc, aHb, aLb, bHb, bHb + 8192, a_kof, b_kof, sA, sB);
        __syncthreads();
        if (kc < 7) {
            if (kc < 6) {
                issue_chunk(sb, X, m0, whi, wlo, n0g, kc + 2, tid);
                CP_WAIT1();
            } else {
                CP_WAIT0();
            }
            __syncthreads();
            convert_chunk(smem, (kc + 1) & 1, tid);
            __syncthreads();
        }
    }
    gemm_epilogue(acc, bias_s, sum_s, sq_s, Y, m0, n0g, set,
                  warp_m, warp_n, lane, tid);
}

// ---------------- gemm_o: A pre-split bf16 hi/lo (from attention) -----------
// Pure cp.async fills for BOTH A and B; no ARAW, no convert phase.
#define SO_BIAS  0
#define SO_SUM   512
#define SO_SQ    1024
#define SO_A     2048                 // 2 bufs x (AH 8K + AL 8K) = 32768
#define SO_B     (SO_A + 32768)       // 2 bufs x (BH 8K + BL 8K) = 32768
#define SO_TOT   (SO_B + 32768)       // 67584 bytes

__device__ __forceinline__ void issue_chunk_o(
    uint32_t sb, const unsigned short* __restrict__ ahi,
    const unsigned short* __restrict__ alo, int m0,
    const unsigned short* __restrict__ whi,
    const unsigned short* __restrict__ wlo, int n0g, int kc, int tid)
{
    const int buf = kc & 1;
    // A: 1024 tasks (2 halves x 128 m-rows x 4 segs of 16B)
#pragma unroll
    for (int i = 0; i < 4; i++) {
        int task = tid + (i << 8);
        int half = task >> 9;
        int rem  = task & 511;
        int r = rem >> 2, seg = rem & 3;
        const unsigned short* src = half ? alo : ahi;
        int off = r * 64 + ((seg * 16) ^ (((r >> 1) & 3) << 4));
        cp16(sb + SO_A + buf * 16384 + half * 8192 + off,
             &src[(size_t)(m0 + r) * 256 + kc * 32 + seg * 8]);
    }
    // B: 1024 tasks
#pragma unroll
    for (int i = 0; i < 4; i++) {
        int task = tid + (i << 8);
        int half = task >> 9;
        int rem  = task & 511;
        int r = rem >> 2, seg = rem & 3;
        const unsigned short* src = half ? wlo : whi;
        int off = r * 64 + ((seg * 16) ^ (((r >> 1) & 3) << 4));
        cp16(sb + SO_B + buf * 16384 + half * 8192 + off,
             &src[(size_t)(n0g + r) * 256 + kc * 32 + seg * 8]);
    }
    CP_COMMIT();
}

__global__ __launch_bounds__(256, 2) void gemm_o_kernel(
    const unsigned short* __restrict__ ahi,
    const unsigned short* __restrict__ alo,
    const float* __restrict__ bo, float* __restrict__ out)
{
    extern __shared__ char smem[];
    const uint32_t sb = smem_u32(smem);
    const unsigned short* whi = &g_Whi[3][0];
    const unsigned short* wlo = &g_Wlo[3][0];

    const int tid  = threadIdx.x;
    const int wid  = tid >> 5, lane = tid & 31;
    const int m0   = (blockIdx.x >> 1) * 128;
    const int n0g  = (blockIdx.x & 1) * 128;
    const int warp_m = wid & 3;
    const int warp_n = wid >> 2;

    float* bias_s = (float*)(smem + SO_BIAS);
    float* sum_s  = (float*)(smem + SO_SUM);
    float* sq_s   = (float*)(smem + SO_SQ);
    if (tid < 128) {
        bias_s[tid] = bo[n0g + tid];
        sum_s[tid] = 0.f;
        sq_s[tid]  = 0.f;
    }

    float acc[2][8][4];
#pragma unroll
    for (int a = 0; a < 2; a++)
#pragma unroll
        for (int b = 0; b < 8; b++)
#pragma unroll
            for (int c = 0; c < 4; c++) acc[a][b][c] = 0.f;

    issue_chunk_o(sb, ahi, alo, m0, whi, wlo, n0g, 0, tid);
    issue_chunk_o(sb, ahi, alo, m0, whi, wlo, n0g, 1, tid);
    CP_WAIT1();
    __syncthreads();

    const int a_row = (warp_m * 32) + (lane & 7) + ((lane >> 3) & 1) * 8;
    const int a_kof = (lane >> 4) * 16;
    const int b_row = (warp_n * 64) + (lane & 7) + ((lane >> 4) & 1) * 8;
    const int b_kof = ((lane >> 3) & 1) * 16;
    const int sA = ((a_row >> 1) & 3) << 4;
    const int sB = ((b_row >> 1) & 3) << 4;

    for (int kc = 0; kc < 8; kc++) {
        const uint32_t aHb = sb + SO_A + (kc & 1) * 16384 + a_row * 64;
        const uint32_t bHb = sb + SO_B + (kc & 1) * 16384 + b_row * 64;
        mma_chunk(acc, aHb, aHb + 8192, bHb, bHb + 8192, a_kof, b_kof, sA, sB);
        __syncthreads();
        if (kc < 7) {
            if (kc < 6) {
                issue_chunk_o(sb, ahi, alo, m0, whi, wlo, n0g, kc + 2, tid);
                CP_WAIT1();
            } else {
                CP_WAIT0();
            }
            __syncthreads();
        }
    }
    gemm_epilogue(acc, bias_s, sum_s, sq_s, out, m0, n0g, 3,
                  warp_m, warp_n, lane, tid);
}

// ---------------- finalize BN ------------------------------------------------
__global__ void finalize_bn3_kernel(
    const float* __restrict__ g0, const float* __restrict__ be0,
    const float* __restrict__ g1, const float* __restrict__ be1,
    const float* __restrict__ g2, const float* __restrict__ be2)
{
    int set = blockIdx.x;
    const float* gamma = (set == 0) ? g0 : (set == 1) ? g1 : g2;
    const float* beta  = (set == 0) ? be0 : (set == 1) ? be1 : be2;
    int o = threadIdx.x;
    const float invM = 1.f / (float)MROWS;
    float mu  = g_sum[set][o] * invM;
    float var = g_sumsq[set][o] * invM - mu * mu;
    float sc = gamma[o] * rsqrtf(var + 1e-5f);
    g_scale[set][o] = sc;
    g_shift[set][o] = beta[o] - mu * sc;
}

__global__ void finalize_bn_kernel(const float* __restrict__ gamma,
                                   const float* __restrict__ beta, int set) {
    int o = threadIdx.x;
    const float invM = 1.f / (float)MROWS;
    float mu  = g_sum[set][o] * invM;
    float var = g_sumsq[set][o] * invM - mu * mu;
    float sc = gamma[o] * rsqrtf(var + 1e-5f);
    g_scale[set][o] = sc;
    g_shift[set][o] = beta[o] - mu * sc;
}

// ---------------- attention: emits O as bf16 hi/lo ---------------------------
__device__ __forceinline__ float4 norm_relu4(float4 y, float4 s, float4 t) {
    float4 r;
    r.x = fmaxf(fmaf(y.x, s.x, t.x), 0.f);
    r.y = fmaxf(fmaf(y.y, s.y, t.y), 0.f);
    r.z = fmaxf(fmaf(y.z, s.z, t.z), 0.f);
    r.w = fmaxf(fmaf(y.w, s.w, t.w), 0.f);
    return r;
}

#define ATT_ROW 196
#define ATT_TEN (32 * ATT_ROW)
#define OUT_ROW 260
#define ATT_OUT (24 * OUT_ROW)
#define ATT_SMEM ((3 * ATT_TEN + ATT_OUT) * 4)   // 100224 bytes

__global__ __launch_bounds__(384, 2) void attn_kernel(
    const float* __restrict__ Yq, const float* __restrict__ Yk,
    const float* __restrict__ Yv,
    unsigned short* __restrict__ Ohi, unsigned short* __restrict__ Olo)
{
    extern __shared__ float asm_s[];
    float* qs = asm_s;
    float* ks = asm_s + ATT_TEN;
    float* vs = asm_s + 2 * ATT_TEN;
    float* out_s = asm_s + 3 * ATT_TEN;

    const int tid = threadIdx.x;
    const int pair = blockIdx.x;
    const int b = pair / NN;
    const int n = pair - b * NN;
    const float QSC = 0.17677669529663687f * 1.4426950408889634f;

#pragma unroll
    for (int i = 0; i < 4; i++) {
        int f  = tid + i * 384;
        int l  = f >> 6;
        int q4 = f & 63;
        int d0 = q4 << 2;
        int c  = d0 >> 3, h0 = d0 & 7;
        int so = c * ATT_ROW + l * 8 + h0;
        size_t g = ((size_t)(b * LL + l) * NN + n) * DDIM + d0;

        float4 sq = *reinterpret_cast<const float4*>(&g_scale[0][d0]);
        float4 tq = *reinterpret_cast<const float4*>(&g_shift[0][d0]);
        float4 sk = *reinterpret_cast<const float4*>(&g_scale[1][d0]);
        float4 tk = *reinterpret_cast<const float4*>(&g_shift[1][d0]);
        float4 sv = *reinterpret_cast<const float4*>(&g_scale[2][d0]);
        float4 tv = *reinterpret_cast<const float4*>(&g_shift[2][d0]);

        float4 yq = *reinterpret_cast<const float4*>(&Yq[g]);
        float4 yk = *reinterpret_cast<const float4*>(&Yk[g]);
        float4 yv = *reinterpret_cast<const float4*>(&Yv[g]);

        float4 qn = norm_relu4(yq, sq, tq);
        qn.x *= QSC; qn.y *= QSC; qn.z *= QSC; qn.w *= QSC;
        *reinterpret_cast<float4*>(&qs[so]) = qn;
        *reinterpret_cast<float4*>(&ks[so]) = norm_relu4(yk, sk, tk);
        *reinterpret_cast<float4*>(&vs[so]) = norm_relu4(yv, sv, tv);
    }
    __syncthreads();

    const int c0 = tid / 24;
    const int lf = tid - c0 * 24;

#pragma unroll
    for (int t = 0; t < 2; t++) {
        const int c = c0 + t * 16;
        const float* qr = &qs[c * ATT_ROW + lf * 8];
        float4 q0 = *reinterpret_cast<const float4*>(qr);
        float4 q1 = *reinterpret_cast<const float4*>(qr + 4);

        float sc[24];
        float mx = -1e30f;
#pragma unroll
        for (int pp = 0; pp < 24; pp++) {
            const float* kr = &ks[c * ATT_ROW + pp * 8];
            float4 k0 = *reinterpret_cast<const float4*>(kr);
            float4 k1 = *reinterpret_cast<const float4*>(kr + 4);
            float s = q0.x * k0.x + q0.y * k0.y + q0.z * k0.z + q0.w * k0.w +
                      q1.x * k1.x + q1.y * k1.y + q1.z * k1.z + q1.w * k1.w;
            sc[pp] = s;
            mx = fmaxf(mx, s);
        }
        float ssum = 0.f;
#pragma unroll
        for (int pp = 0; pp < 24; pp++) {
            float e = ex2(sc[pp] - mx);
            sc[pp] = e;
            ssum += e;
        }
        float inv = 1.f / ssum;
        float o[8] = {0.f, 0.f, 0.f, 0.f, 0.f, 0.f, 0.f, 0.f};
#pragma unroll
        for (int pp = 0; pp < 24; pp++) {
            float a = sc[pp] * inv;
            const float* vr = &vs[c * ATT_ROW + pp * 8];
            float4 v0 = *reinterpret_cast<const float4*>(vr);
            float4 v1 = *reinterpret_cast<const float4*>(vr + 4);
            o[0] = fmaf(a, v0.x, o[0]);
            o[1] = fmaf(a, v0.y, o[1]);
            o[2] = fmaf(a, v0.z, o[2]);
            o[3] = fmaf(a, v0.w, o[3]);
            o[4] = fmaf(a, v1.x, o[4]);
            o[5] = fmaf(a, v1.y, o[5]);
            o[6] = fmaf(a, v1.z, o[6]);
            o[7] = fmaf(a, v1.w, o[7]);
        }
        float* op = &out_s[lf * OUT_ROW + c * 8];
        *reinterpret_cast<float4*>(op)     = make_float4(o[0], o[1], o[2], o[3]);
        *reinterpret_cast<float4*>(op + 4) = make_float4(o[4], o[5], o[6], o[7]);
    }
    __syncthreads();

    // coalesced global stores: convert fp32 -> bf16 hi/lo on the fly
#pragma unroll
    for (int i = 0; i < 4; i++) {
        int f  = tid + i * 384;
        int l  = f >> 6;
        int q4 = f & 63;
        float4 v = *reinterpret_cast<const float4*>(&out_s[l * OUT_ROW + q4 * 4]);
        uint32_t h01 = cvt2bf(v.x, v.y);
        uint32_t h23 = cvt2bf(v.z, v.w);
        float f0 = __uint_as_float(h01 << 16);
        float f1 = __uint_as_float(h01 & 0xFFFF0000u);
        float f2 = __uint_as_float(h23 << 16);
        float f3 = __uint_as_float(h23 & 0xFFFF0000u);
        uint32_t l01 = cvt2bf(v.x - f0, v.y - f1);
        uint32_t l23 = cvt2bf(v.z - f2, v.w - f3);
        size_t g = ((size_t)(b * LL + l) * NN + n) * DDIM + q4 * 4;
        *reinterpret_cast<uint2*>(&Ohi[g]) = make_uint2(h01, h23);
        *reinterpret_cast<uint2*>(&Olo[g]) = make_uint2(l01, l23);
    }
}

// ---------------- final normalize + relu, IN PLACE on d_out -----------------
__global__ __launch_bounds__(256) void norm_out_kernel(float* __restrict__ out)
{
    size_t i = (size_t)blockIdx.x * 256 + threadIdx.x;
    size_t idx = i * 4;
    int d = (int)(idx & 255);
    float4 z = *reinterpret_cast<const float4*>(&out[idx]);
    float4 s = *reinterpret_cast<const float4*>(&g_scale[3][d]);
    float4 t = *reinterpret_cast<const float4*>(&g_shift[3][d]);
    float4 r;
    r.x = fmaxf(fmaf(z.x, s.x, t.x), 0.f);
    r.y = fmaxf(fmaf(z.y, s.y, t.y), 0.f);
    r.z = fmaxf(fmaf(z.z, s.z, t.z), 0.f);
    r.w = fmaxf(fmaf(z.w, s.w, t.w), 0.f);
    *reinterpret_cast<float4*>(&out[idx]) = r;
}

// ---------------- launch ------------------------------------------------------
extern "C" void kernel_launch(void* const* d_in, const int* in_sizes, int n_in,
                              void* d_out, int out_size)
{
    const float* x   = (const float*)d_in[0];
    const float* sp  = (const float*)d_in[1];
    const float* sf  = (const float*)d_in[2];
    const float* Wq  = (const float*)d_in[3];
    const float* bq  = (const float*)d_in[4];
    const float* gq  = (const float*)d_in[5];
    const float* beq = (const float*)d_in[6];
    const float* Wk  = (const float*)d_in[7];
    const float* bk  = (const float*)d_in[8];
    const float* gk  = (const float*)d_in[9];
    const float* bek = (const float*)d_in[10];
    const float* Wv  = (const float*)d_in[11];
    const float* bv  = (const float*)d_in[12];
    const float* gv  = (const float*)d_in[13];
    const float* bev = (const float*)d_in[14];
    const float* Wo  = (const float*)d_in[15];
    const float* bo  = (const float*)d_in[16];
    const float* go  = (const float*)d_in[17];
    const float* beo = (const float*)d_in[18];
    float* out = (float*)d_out;

    float *Yq, *Yk, *Yv, *Obuf;
    cudaGetSymbolAddress((void**)&Yq, g_bufQ);
    cudaGetSymbolAddress((void**)&Yk, g_bufK);
    cudaGetSymbolAddress((void**)&Yv, g_bufV);
    cudaGetSymbolAddress((void**)&Obuf, g_bufO);
    unsigned short* Ohi = (unsigned short*)Obuf;
    unsigned short* Olo = Ohi + (size_t)MROWS * DDIM;

    cudaFuncSetAttribute(gemm_qkv_kernel,
                         cudaFuncAttributeMaxDynamicSharedMemorySize, SM_TOT);
    cudaFuncSetAttribute(gemm_o_kernel,
                         cudaFuncAttributeMaxDynamicSharedMemorySize, SO_TOT);
    cudaFuncSetAttribute(attn_kernel,
                         cudaFuncAttributeMaxDynamicSharedMemorySize, ATT_SMEM);

    conv_w_kernel<<<dim3(64, 2), 256>>>(Wq, Wk, 0);
    conv_w_kernel<<<dim3(64, 2), 256>>>(Wv, Wo, 2);
    zero_stats_kernel<<<1, 256>>>();

    const int gblocks = (MROWS / 128) * 2;   // 1950

    gemm_qkv_kernel<<<dim3(gblocks, 3), 256, SM_TOT>>>(sf, sp, x, bq, bk, bv);

    finalize_bn3_kernel<<<3, 256>>>(gq, beq, gk, bek, gv, bev);

    attn_kernel<<<NPAIRS, 384, ATT_SMEM>>>(Yq, Yk, Yv, Ohi, Olo);

    gemm_o_kernel<<<gblocks, 256, SO_TOT>>>(Ohi, Olo, bo, out);
    finalize_bn_kernel<<<1, 256>>>(go, beo, 3);

    norm_out_kernel<<<(MROWS * DDIM) / (4 * 256), 256>>>(out);
}